// round 13
// baseline (speedup 1.0000x reference)
#include <cuda_runtime.h>
#include <cstdint>

// Problem constants
#define Bn 8
#define Cn 256
#define Hn 96
#define Wn 128
#define Dd 4
#define NS 9      // 2*D+1
#define Qn 81     // NS*NS
#define HW (Hn*Wn)

// Tiling: 2 rows per block; RX=8; 256 consumer + 64 producer threads
#define TY 2
#define RX 8
#define XG (Wn/RX)            // 16
#define CONS 256              // 8 consumer warps (dy 0..7; dy=8 spread)
#define PROD 64               // 2 producer warps
#define NTHREADS (CONS+PROD)  // 320
#define CC 16
#define NCHUNK (Cn/CC)        // 16
#define FBW (Wn + 2*Dd)       // 136
#define FBH (TY + 2*Dd)       // 10
#define VW (RX + 2*Dd)        // 16

#define FA_FLOATS (CC*TY*Wn)          // 4096
#define FB_FLOATS (CC*FBH*FBW)        // 21760
#define STAGE_FLOATS (FA_FLOATS + FB_FLOATS)   // 25856
#define NORM_FLOATS (TY*Wn)           // 256 (inva tile)
#define SMEM_BYTES ((2*STAGE_FLOATS + NORM_FLOATS)*4)  // 207872

// per-channel loader slots: fa 64, fb 340 -> 404 total
#define FA_SL (TY*(Wn/4))             // 64 (== PROD)
#define FB_SL (FBH*(FBW/4))           // 340
#define TOT_SL (FA_SL+FB_SL)          // 404
#define PSL 7                         // ceil(404/64)

// named barrier ids (0 reserved)
#define BFULL0 1
#define BFULL1 2
#define BEMPTY0 3
#define BEMPTY1 4
#define BNORM 5

// norm_b kernel config
#define NB_THREADS 256
#define NB_SLICES 8
#define NB_CPS (Cn/NB_SLICES)         // 32

// Per-pixel inverse norms for fb (scratch)
__device__ float g_invb[Bn*HW];

// bank-quad swizzle on 16B-unit index within a row
__device__ __host__ __forceinline__ int sw(int u) { return u ^ ((u >> 3) & 1); }

// ---------------------------------------------------------------------------
__device__ __forceinline__ void cp16(uint32_t saddr, const float* g, int nbytes) {
    asm volatile("cp.async.cg.shared.global [%0], [%1], 16, %2;"
                 :: "r"(saddr), "l"(g), "r"(nbytes));
}
__device__ __forceinline__ void bar_sync(int id) {
    asm volatile("bar.sync %0, %1;" :: "r"(id), "n"(NTHREADS) : "memory");
}
__device__ __forceinline__ void bar_arrive(int id) {
    asm volatile("bar.arrive %0, %1;" :: "r"(id), "n"(NTHREADS) : "memory");
}

// ---------------------------------------------------------------------------
// Pass 1: per-pixel inverse L2 norms for fb, channel-split 8-way.
// ---------------------------------------------------------------------------
__global__ void norm_b_kernel(const float* __restrict__ fb) {
    __shared__ float2 red[NB_THREADS];
    const int b     = blockIdx.y;
    const int lane  = threadIdx.x & 31;
    const int slice = threadIdx.x >> 5;
    const int p2    = blockIdx.x * 32 + lane;

    const float2* pb = (const float2*)(fb + (size_t)b * Cn * HW) + p2
                     + (size_t)slice * NB_CPS * (HW / 2);
    float s0 = 0.f, s1 = 0.f;
#pragma unroll
    for (int c = 0; c < NB_CPS; c++) {
        float2 v = pb[(size_t)c * (HW / 2)];
        s0 = fmaf(v.x, v.x, s0);
        s1 = fmaf(v.y, v.y, s1);
    }
    red[threadIdx.x] = make_float2(s0, s1);
    __syncthreads();
    if (threadIdx.x < 32) {
        float a0 = 0.f, a1 = 0.f;
#pragma unroll
        for (int s = 0; s < NB_SLICES; s++) {
            float2 v = red[lane + 32 * s];
            a0 += v.x; a1 += v.y;
        }
        float2 o;
        o.x = 1.0f / fmaxf(sqrtf(a0), 1e-12f);
        o.y = 1.0f / fmaxf(sqrtf(a1), 1e-12f);
        ((float2*)g_invb)[b * (HW / 2) + p2] = o;
    }
}

// ---------------------------------------------------------------------------
// Pass 2: warp-specialized correlation, SMSP-balanced.
// Consumer warps 0..7: dy = warp id (2 warps per SMSP).
// dy=8 spread over warps 2,6,3,7 (the producer-free SMSPs), 3 dx each.
// ---------------------------------------------------------------------------
__global__ void __launch_bounds__(NTHREADS, 1)
corr_kernel(const float* __restrict__ fa,
            const float* __restrict__ fb,
            float* __restrict__ out) {
    extern __shared__ float smem[];

    const int b   = blockIdx.y;
    const int y0  = blockIdx.x * TY;
    const int tid = threadIdx.x;

    const size_t baseA = (size_t)b * Cn * HW;
    const uint32_t smem_u = (uint32_t)__cvta_generic_to_shared(smem);
    float* s_norm = smem + 2 * STAGE_FLOATS;   // inva tile [TY*Wn]

    if (tid >= CONS) {
        // ================= PRODUCER =================
        const int ptid = tid - CONS;   // 0..63
        const float* ld_ptr[PSL];
        int ld_s[PSL], ld_str[PSL], ld_nb[PSL];
#pragma unroll
        for (int k = 0; k < PSL; k++) {
            int slot = ptid + k * PROD;
            ld_ptr[k] = nullptr; ld_s[k] = 0; ld_str[k] = 0; ld_nb[k] = -1;
            if (slot < TOT_SL) {
                if (slot < FA_SL) {
                    int yy = slot / (Wn / 4);
                    int u  = slot % (Wn / 4);
                    ld_nb[k]  = 16;
                    ld_ptr[k] = fa + baseA + (y0 + yy) * Wn + u * 4;
                    ld_s[k]   = yy * Wn + sw(u) * 4;
                    ld_str[k] = TY * Wn;
                } else {
                    int u  = slot - FA_SL;
                    int hr = u / (FBW / 4);
                    int kk = u % (FBW / 4);
                    int yy = y0 - Dd + hr;
                    bool valid = (yy >= 0) && (yy < Hn) && (kk >= 1) && (kk <= Wn / 4);
                    ld_nb[k]  = valid ? 16 : 0;   // zfill halo/OOB
                    int yyc = min(max(yy, 0), Hn - 1);
                    int kc  = min(max(kk, 1), Wn / 4);
                    ld_ptr[k] = fb + baseA + yyc * Wn + kc * 4 - 4;
                    ld_s[k]   = FA_FLOATS + hr * FBW + sw(kk) * 4;
                    ld_str[k] = FBH * FBW;
                }
            }
        }

        const int fa_yy = ptid / (Wn / 4);
        const int fa_u  = ptid % (Wn / 4);
        const int fa_sofs = fa_yy * Wn + sw(fa_u) * 4;
        float sq[4] = {0.f, 0.f, 0.f, 0.f};

        int st = 0;
        for (int ch = 0; ch < NCHUNK; ch++) {
            bar_sync(BEMPTY0 + st);
            const int c0 = ch * CC;
            const uint32_t sb = smem_u + (uint32_t)(st * STAGE_FLOATS * 4);
#pragma unroll
            for (int k = 0; k < PSL; k++) {
                if (ld_nb[k] >= 0) {
                    const float* g = ld_ptr[k] + (size_t)c0 * HW;
                    const uint32_t sofs = sb + (uint32_t)(ld_s[k] * 4);
#pragma unroll
                    for (int cc = 0; cc < CC; cc++)
                        cp16(sofs + (uint32_t)(cc * ld_str[k] * 4),
                             g + (size_t)cc * HW, ld_nb[k]);
                }
            }
            asm volatile("cp.async.commit_group;");
            asm volatile("cp.async.wait_group 0;");
            bar_arrive(BFULL0 + st);

            const float* sfa = smem + st * STAGE_FLOATS + fa_sofs;
#pragma unroll
            for (int cc = 0; cc < CC; cc++) {
                float4 v = *(const float4*)(sfa + cc * (TY * Wn));
                sq[0] = fmaf(v.x, v.x, sq[0]);
                sq[1] = fmaf(v.y, v.y, sq[1]);
                sq[2] = fmaf(v.z, v.z, sq[2]);
                sq[3] = fmaf(v.w, v.w, sq[3]);
            }
            st ^= 1;
        }

        float4 iv;
        iv.x = 1.0f / fmaxf(sqrtf(sq[0]), 1e-12f);
        iv.y = 1.0f / fmaxf(sqrtf(sq[1]), 1e-12f);
        iv.z = 1.0f / fmaxf(sqrtf(sq[2]), 1e-12f);
        iv.w = 1.0f / fmaxf(sqrtf(sq[3]), 1e-12f);
        *(float4*)(s_norm + fa_yy * Wn + fa_u * 4) = iv;
        bar_arrive(BNORM);
        return;
    }

    // ================= CONSUMER =================
    const int w  = tid / 32;                 // 0..7, dy = w
    const int dy = w;
    const int r  = tid % 32;
    const int yl = r / XG;                   // 0..1
    const int xg = r % XG;                   // 0..15
    const int x0 = xg * RX;

    // dy=8 slice assignment (warps on producer-free SMSPs 2,3)
    // w2: compute dx 0..2 write 0..1 | w6: 2..4 write 2..3
    // w3: 4..6 write 4..5            | w7: 6..8 write 6..8
    int B = -1;
    if (w == 2) B = 0; else if (w == 6) B = 2;
    else if (w == 3) B = 4; else if (w == 7) B = 6;
    const bool sp = (B >= 0);
    const int wr8 = (w == 7) ? 3 : 2;
    const int Bc = sp ? B : 0;

    // swizzled, channel-invariant float offsets
    int faO[2], fbO[4], fb8O[5];
#pragma unroll
    for (int j = 0; j < 2; j++)
        faO[j] = yl * Wn + sw(2 * xg + j) * 4;
#pragma unroll
    for (int j = 0; j < 4; j++)
        fbO[j] = (yl + dy) * FBW + sw(2 * xg + j) * 4;
#pragma unroll
    for (int k = 0; k < 5; k++) {
        int f = x0 + Bc + 2 * k;             // even -> float2 aligned
        fb8O[k] = (yl + 8) * FBW + sw(f >> 2) * 4 + (f & 3);
    }

    float acc[NS][RX];
#pragma unroll
    for (int d = 0; d < NS; d++)
#pragma unroll
        for (int i = 0; i < RX; i++) acc[d][i] = 0.f;
    float acc8[3][RX];
#pragma unroll
    for (int d = 0; d < 3; d++)
#pragma unroll
        for (int i = 0; i < RX; i++) acc8[d][i] = 0.f;

    bar_arrive(BEMPTY0);
    bar_arrive(BEMPTY1);

    int st = 0;
    for (int ch = 0; ch < NCHUNK; ch++) {
        bar_sync(BFULL0 + st);

        const float* s_fa = smem + st * STAGE_FLOATS;
        const float* s_fb = s_fa + FA_FLOATS;

        // ---- own-dy main loop (register double-buffered) ----
        float4 A0, A1, V0, V1, V2, V3;
        A0 = *(const float4*)(s_fa + faO[0]);
        A1 = *(const float4*)(s_fa + faO[1]);
        V0 = *(const float4*)(s_fb + fbO[0]);
        V1 = *(const float4*)(s_fb + fbO[1]);
        V2 = *(const float4*)(s_fb + fbO[2]);
        V3 = *(const float4*)(s_fb + fbO[3]);

#pragma unroll
        for (int cc = 0; cc < CC; cc++) {
            float4 A0n, A1n, V0n, V1n, V2n, V3n;
            if (cc + 1 < CC) {
                const float* fap = s_fa + (cc + 1) * (TY * Wn);
                const float* fbp = s_fb + (cc + 1) * (FBH * FBW);
                A0n = *(const float4*)(fap + faO[0]);
                A1n = *(const float4*)(fap + faO[1]);
                V0n = *(const float4*)(fbp + fbO[0]);
                V1n = *(const float4*)(fbp + fbO[1]);
                V2n = *(const float4*)(fbp + fbO[2]);
                V3n = *(const float4*)(fbp + fbO[3]);
            }
            float a[RX] = {A0.x, A0.y, A0.z, A0.w, A1.x, A1.y, A1.z, A1.w};
            float v[VW] = {V0.x, V0.y, V0.z, V0.w, V1.x, V1.y, V1.z, V1.w,
                           V2.x, V2.y, V2.z, V2.w, V3.x, V3.y, V3.z, V3.w};
#pragma unroll
            for (int dx = 0; dx < NS; dx++)
#pragma unroll
                for (int i = 0; i < RX; i++)
                    acc[dx][i] = fmaf(a[i], v[dx + i], acc[dx][i]);
            if (cc + 1 < CC) {
                A0 = A0n; A1 = A1n; V0 = V0n; V1 = V1n; V2 = V2n; V3 = V3n;
            }
        }

        // ---- dy=8 slice (special warps only; warp-uniform branch) ----
        if (sp) {
#pragma unroll 4
            for (int cc = 0; cc < CC; cc++) {
                const float* fap = s_fa + cc * (TY * Wn);
                const float* fbp = s_fb + cc * (FBH * FBW);
                float4 Aa = *(const float4*)(fap + faO[0]);
                float4 Ab = *(const float4*)(fap + faO[1]);
                float2 p0 = *(const float2*)(fbp + fb8O[0]);
                float2 p1 = *(const float2*)(fbp + fb8O[1]);
                float2 p2 = *(const float2*)(fbp + fb8O[2]);
                float2 p3 = *(const float2*)(fbp + fb8O[3]);
                float2 p4 = *(const float2*)(fbp + fb8O[4]);
                float a[RX] = {Aa.x, Aa.y, Aa.z, Aa.w, Ab.x, Ab.y, Ab.z, Ab.w};
                float v8[10] = {p0.x, p0.y, p1.x, p1.y, p2.x,
                                p2.y, p3.x, p3.y, p4.x, p4.y};
#pragma unroll
                for (int dxl = 0; dxl < 3; dxl++)
#pragma unroll
                    for (int i = 0; i < RX; i++)
                        acc8[dxl][i] = fmaf(a[i], v8[dxl + i], acc8[dxl][i]);
            }
        }

        bar_arrive(BEMPTY0 + st);
        st ^= 1;
    }

    // wait for producers to publish inva
    bar_sync(BNORM);

    // ---- epilogue: own dy ----
    const int y = y0 + yl;
    float ia[RX];
#pragma unroll
    for (int i = 0; i < RX; i++) ia[i] = s_norm[yl * Wn + x0 + i];

    const int sy = y + dy - Dd;
    const bool rowok = (unsigned)sy < (unsigned)Hn;
    float ib[VW];
#pragma unroll
    for (int k = 0; k < VW; k++) {
        int sx = x0 + k - Dd;
        ib[k] = (rowok && (unsigned)sx < (unsigned)Wn)
                    ? g_invb[b * HW + sy * Wn + sx] : 0.f;
    }

#pragma unroll
    for (int dx = 0; dx < NS; dx++) {
        float o[RX];
#pragma unroll
        for (int i = 0; i < RX; i++)
            o[i] = acc[dx][i] * ia[i] * ib[dx + i];
        const int q = dy * NS + dx;
        float* op = out + ((size_t)(b * Qn + q) * Hn + y) * Wn + x0;
        *(float4*)(op)     = make_float4(o[0], o[1], o[2], o[3]);
        *(float4*)(op + 4) = make_float4(o[4], o[5], o[6], o[7]);
    }

    // ---- epilogue: dy=8 slice ----
    if (sp) {
        const int sy8 = y + 8 - Dd;          // y + 4
        const bool rowok8 = sy8 < Hn;
        float ib8[10];
#pragma unroll
        for (int j = 0; j < 10; j++) {
            int sx = x0 + B + j - Dd;
            ib8[j] = (rowok8 && (unsigned)sx < (unsigned)Wn)
                         ? g_invb[b * HW + sy8 * Wn + sx] : 0.f;
        }
#pragma unroll
        for (int dxl = 0; dxl < 3; dxl++) {
            if (dxl < wr8) {
                float o[RX];
#pragma unroll
                for (int i = 0; i < RX; i++)
                    o[i] = acc8[dxl][i] * ia[i] * ib8[dxl + i];
                const int q = 8 * NS + B + dxl;
                float* op = out + ((size_t)(b * Qn + q) * Hn + y) * Wn + x0;
                *(float4*)(op)     = make_float4(o[0], o[1], o[2], o[3]);
                *(float4*)(op + 4) = make_float4(o[4], o[5], o[6], o[7]);
            }
        }
    }
}

// ---------------------------------------------------------------------------
extern "C" void kernel_launch(void* const* d_in, const int* in_sizes, int n_in,
                              void* d_out, int out_size) {
    const float* fa = (const float*)d_in[0];
    const float* fb = (const float*)d_in[1];
    float* out = (float*)d_out;

    norm_b_kernel<<<dim3(HW / 2 / 32, Bn), NB_THREADS>>>(fb);

    cudaFuncSetAttribute(corr_kernel,
                         cudaFuncAttributeMaxDynamicSharedMemorySize,
                         SMEM_BYTES);
    corr_kernel<<<dim3(Hn / TY, Bn), NTHREADS, SMEM_BYTES>>>(fa, fb, out);
}